// round 8
// baseline (speedup 1.0000x reference)
#include <cuda_runtime.h>

// Shapes (fixed for this problem)
#define B_   16
#define C_   256
#define HW_  4096
#define K_   1024
#define NPIX (B_ * HW_)          // 65536
#define ZQ_ELEMS (NPIX * C_)     // 16777216

// Scratch (no allocations allowed)
__device__ float  g_e2[K_];
__device__ int    g_idx[NPIX];
__device__ double g_loss;

// ---- packed f32x2 helpers (sm_103a FFMA2 path; bit-exact fp32) -------------
__device__ __forceinline__ unsigned long long pk2(float lo, float hi) {
    unsigned long long r;
    asm("mov.b64 %0, {%1, %2};" : "=l"(r) : "f"(lo), "f"(hi));
    return r;
}
__device__ __forceinline__ void upk2(float& lo, float& hi, unsigned long long v) {
    asm("mov.b64 {%0, %1}, %2;" : "=f"(lo), "=f"(hi) : "l"(v));
}
__device__ __forceinline__ void ffma2(unsigned long long& d,
                                      unsigned long long a,
                                      unsigned long long b) {
    asm("fma.rn.f32x2 %0, %1, %2, %3;" : "=l"(d) : "l"(a), "l"(b), "l"(d));
}

// ---------------------------------------------------------------------------
// Kernel 0: embedding squared norms + reset loss accumulator.
// ---------------------------------------------------------------------------
__global__ void vq_e2_kernel(const float* __restrict__ E) {
    int k = blockIdx.x;
    int lane = threadIdx.x;
    const float* row = E + (size_t)k * C_;
    float s = 0.f;
    #pragma unroll
    for (int c = lane; c < C_; c += 32) {
        float v = __ldg(row + c);
        s = fmaf(v, v, s);
    }
    #pragma unroll
    for (int off = 16; off; off >>= 1)
        s += __shfl_down_sync(0xffffffffu, s, off);
    if (lane == 0) g_e2[k] = s;
    if (k == 0 && lane == 0) g_loss = 0.0;
}

// ---------------------------------------------------------------------------
// Kernel 1: fused GEMM + argmin, FFMA2 (fma.rn.f32x2) mainloop.
// Block: 256 threads, tile = 128 pixels x 128 codes.
// Thread (tx,ty): pixels {2*ty + 32*i + h} (4 adjacent pairs -> LDS.64),
//                 codes  {tx + 16*j}, j=0..7.
// Distance d = ||e||^2 - 2 x.e  (x^2 per-pixel constant; dropped).
// All arithmetic remains exact fp32 -> argmin identical to scalar version.
// ---------------------------------------------------------------------------
#define TP 128   // pixels per block
#define KT 128   // codes per tile
#define CK 32    // c-chunk

__global__ __launch_bounds__(256, 2)
void vq_argmin_kernel(const float* __restrict__ X, const float* __restrict__ E) {
    __shared__ __align__(16) float xs[CK][TP];     // [c][pixel]
    __shared__ float es[CK][KT + 1];               // [c][code], pad: fill conflicts

    const int tid = threadIdx.x;
    const int tx = tid & 15;            // code group
    const int ty = tid >> 4;            // pixel-pair group
    const int n0 = blockIdx.x * TP;     // 4096 % 128 == 0 -> tile within one b
    const int b  = n0 / HW_;
    const int p0 = n0 % HW_;
    const float* xbase = X + (size_t)b * C_ * HW_ + p0;

    float bestv[8];                     // index = i*2 + h
    int   besti[8];
    #pragma unroll
    for (int i = 0; i < 8; ++i) { bestv[i] = 3.4e38f; besti[i] = 0; }

    for (int kt = 0; kt < K_; kt += KT) {
        unsigned long long acc2[4][8];  // packed pixel-pair accumulators
        #pragma unroll
        for (int i = 0; i < 4; ++i)
            #pragma unroll
            for (int j = 0; j < 8; ++j) acc2[i][j] = 0ull;

        for (int cc = 0; cc < C_; cc += CK) {
            __syncthreads();   // protect smem from previous chunk's readers
            // fill xs: 32x128 floats, coalesced
            #pragma unroll
            for (int l = 0; l < (CK * TP) / 256; ++l) {
                int ii = tid + l * 256;
                int c = ii >> 7, p = ii & 127;
                xs[c][p] = __ldg(xbase + (size_t)(cc + c) * HW_ + p);
            }
            // fill es: 128 codes x 32 c, transposed [c][k], conflict-free (pad)
            #pragma unroll
            for (int l = 0; l < (CK * KT) / 256; ++l) {
                int ii = tid + l * 256;
                int k = ii >> 5, c = ii & 31;
                es[c][k] = __ldg(E + (size_t)(kt + k) * C_ + (cc + c));
            }
            __syncthreads();

            #pragma unroll 4
            for (int c = 0; c < CK; ++c) {
                unsigned long long axp[4], ekk[8];
                #pragma unroll
                for (int i = 0; i < 4; ++i) {
                    float2 v = *reinterpret_cast<const float2*>(&xs[c][2 * ty + 32 * i]);
                    axp[i] = pk2(v.x, v.y);
                }
                #pragma unroll
                for (int j = 0; j < 8; ++j) {
                    float e = es[c][tx + j * 16];
                    ekk[j] = pk2(e, e);
                }
                #pragma unroll
                for (int i = 0; i < 4; ++i)
                    #pragma unroll
                    for (int j = 0; j < 8; ++j)
                        ffma2(acc2[i][j], axp[i], ekk[j]);
            }
        }

        // distance + running argmin (ties -> lower index, matching jnp.argmin)
        #pragma unroll
        for (int j = 0; j < 8; ++j) {
            int k = kt + tx + j * 16;
            float e2 = g_e2[k];
            #pragma unroll
            for (int i = 0; i < 4; ++i) {
                float a0, a1;
                upk2(a0, a1, acc2[i][j]);
                float d0 = fmaf(-2.f, a0, e2);
                float d1 = fmaf(-2.f, a1, e2);
                int s0 = i * 2, s1 = i * 2 + 1;
                if (d0 < bestv[s0] || (d0 == bestv[s0] && k < besti[s0])) {
                    bestv[s0] = d0; besti[s0] = k;
                }
                if (d1 < bestv[s1] || (d1 == bestv[s1] && k < besti[s1])) {
                    bestv[s1] = d1; besti[s1] = k;
                }
            }
        }
    }

    // reduce (minval, minidx) across the 16 code-group lanes (same ty)
    #pragma unroll
    for (int s = 0; s < 8; ++s) {
        float v = bestv[s];
        int   ix = besti[s];
        #pragma unroll
        for (int off = 8; off; off >>= 1) {
            float ov = __shfl_down_sync(0xffffffffu, v, off, 16);
            int   oi = __shfl_down_sync(0xffffffffu, ix, off, 16);
            if (ov < v || (ov == v && oi < ix)) { v = ov; ix = oi; }
        }
        if (tx == 0) {
            int i = s >> 1, h = s & 1;
            g_idx[n0 + 2 * ty + 32 * i + h] = ix;
        }
    }
}

// ---------------------------------------------------------------------------
// Kernel 2: gather z_q rows, transpose-write to (b,c,h,w), accumulate loss.
// ---------------------------------------------------------------------------
#define QP 32

__global__ __launch_bounds__(256)
void vq_gather_kernel(const float* __restrict__ X, const float* __restrict__ E,
                      float* __restrict__ out) {
    __shared__ float s[QP][C_ + 5];
    __shared__ int ids[QP];

    const int tid = threadIdx.x;
    const int n0 = blockIdx.x * QP;     // 4096 % 32 == 0 -> within one b
    if (tid < QP) ids[tid] = g_idx[n0 + tid];
    __syncthreads();

    #pragma unroll
    for (int l = 0; l < (QP * C_) / 256; ++l) {
        int ii = tid + l * 256;
        int q = ii >> 8, c = ii & 255;
        s[q][c] = __ldg(E + (size_t)ids[q] * C_ + c);
    }
    __syncthreads();

    const int b = n0 / HW_, p0 = n0 % HW_;
    const size_t obase = (size_t)b * C_ * HW_ + p0;
    const int q  = tid & 31;
    const int c0 = tid >> 5;            // 0..7

    float lsum = 0.f;
    #pragma unroll
    for (int l = 0; l < C_ / 8; ++l) {
        int c = c0 + l * 8;
        float zq = s[q][c];
        size_t a = obase + (size_t)c * HW_ + q;
        float xv = __ldg(X + a);
        out[a] = zq;
        float dd = xv - zq;
        lsum = fmaf(dd, dd, lsum);
    }

    // block reduce -> double atomic
    #pragma unroll
    for (int off = 16; off; off >>= 1)
        lsum += __shfl_down_sync(0xffffffffu, lsum, off);
    __shared__ float ws[8];
    if ((tid & 31) == 0) ws[tid >> 5] = lsum;
    __syncthreads();
    if (tid < 8) {
        float v = ws[tid];
        #pragma unroll
        for (int off = 4; off; off >>= 1)
            v += __shfl_down_sync(0xffu, v, off);
        if (tid == 0) atomicAdd(&g_loss, (double)v);
    }
}

// ---------------------------------------------------------------------------
// Kernel 3: finalize loss. quantization_loss = 2 * mean((zq - x)^2)
// ---------------------------------------------------------------------------
__global__ void vq_loss_kernel(float* __restrict__ out) {
    out[ZQ_ELEMS] = (float)(2.0 * g_loss / (double)ZQ_ELEMS);
}

// ---------------------------------------------------------------------------
extern "C" void kernel_launch(void* const* d_in, const int* in_sizes, int n_in,
                              void* d_out, int out_size) {
    const float* X = (const float*)d_in[0];   // x (16,256,64,64)
    const float* E = (const float*)d_in[1];   // embeddings (1024,256)
    float* out = (float*)d_out;

    vq_e2_kernel<<<K_, 32>>>(E);
    vq_argmin_kernel<<<NPIX / TP, 256>>>(X, E);
    vq_gather_kernel<<<NPIX / QP, 256>>>(X, E, out);
    if (out_size > ZQ_ELEMS)
        vq_loss_kernel<<<1, 1>>>(out);
}

// round 9
// speedup vs baseline: 1.0030x; 1.0030x over previous
#include <cuda_runtime.h>

// Shapes (fixed for this problem)
#define B_   16
#define C_   256
#define HW_  4096
#define K_   1024
#define NPIX (B_ * HW_)          // 65536
#define ZQ_ELEMS (NPIX * C_)     // 16777216

// Scratch (no allocations allowed)
__device__ float  g_e2[K_];
__device__ int    g_idx[NPIX];
__device__ double g_loss;

// ---- packed f32x2 helpers (sm_103a FFMA2 path; bit-exact fp32) -------------
__device__ __forceinline__ unsigned long long pk2(float lo, float hi) {
    unsigned long long r;
    asm("mov.b64 %0, {%1, %2};" : "=l"(r) : "f"(lo), "f"(hi));
    return r;
}
__device__ __forceinline__ void upk2(float& lo, float& hi, unsigned long long v) {
    asm("mov.b64 {%0, %1}, %2;" : "=f"(lo), "=f"(hi) : "l"(v));
}
__device__ __forceinline__ void ffma2(unsigned long long& d,
                                      unsigned long long a,
                                      unsigned long long b) {
    asm("fma.rn.f32x2 %0, %1, %2, %3;" : "=l"(d) : "l"(a), "l"(b), "l"(d));
}

// ---------------------------------------------------------------------------
// Kernel 0: embedding squared norms + reset loss accumulator.
// ---------------------------------------------------------------------------
__global__ void vq_e2_kernel(const float* __restrict__ E) {
    int k = blockIdx.x;
    int lane = threadIdx.x;
    const float* row = E + (size_t)k * C_;
    float s = 0.f;
    #pragma unroll
    for (int c = lane; c < C_; c += 32) {
        float v = __ldg(row + c);
        s = fmaf(v, v, s);
    }
    #pragma unroll
    for (int off = 16; off; off >>= 1)
        s += __shfl_down_sync(0xffffffffu, s, off);
    if (lane == 0) g_e2[k] = s;
    if (k == 0 && lane == 0) g_loss = 0.0;
}

// ---------------------------------------------------------------------------
// Kernel 1: fused GEMM + argmin, FFMA2 (fma.rn.f32x2) mainloop.
// Block: 256 threads, tile = 128 pixels x 128 codes.
// Thread (tx,ty): pixels {2*ty + 32*i + h} (4 adjacent pairs -> LDS.64),
//                 codes  {tx + 16*j}, j=0..7.
// Distance d = ||e||^2 - 2 x.e  (x^2 per-pixel constant; dropped).
// All arithmetic remains exact fp32 -> argmin identical to scalar version.
// ---------------------------------------------------------------------------
#define TP 128   // pixels per block
#define KT 128   // codes per tile
#define CK 32    // c-chunk

__global__ __launch_bounds__(256, 2)
void vq_argmin_kernel(const float* __restrict__ X, const float* __restrict__ E) {
    __shared__ __align__(16) float xs[CK][TP];     // [c][pixel]
    __shared__ float es[CK][KT + 1];               // [c][code], pad: fill conflicts

    const int tid = threadIdx.x;
    const int tx = tid & 15;            // code group
    const int ty = tid >> 4;            // pixel-pair group
    const int n0 = blockIdx.x * TP;     // 4096 % 128 == 0 -> tile within one b
    const int b  = n0 / HW_;
    const int p0 = n0 % HW_;
    const float* xbase = X + (size_t)b * C_ * HW_ + p0;

    float bestv[8];                     // index = i*2 + h
    int   besti[8];
    #pragma unroll
    for (int i = 0; i < 8; ++i) { bestv[i] = 3.4e38f; besti[i] = 0; }

    for (int kt = 0; kt < K_; kt += KT) {
        unsigned long long acc2[4][8];  // packed pixel-pair accumulators
        #pragma unroll
        for (int i = 0; i < 4; ++i)
            #pragma unroll
            for (int j = 0; j < 8; ++j) acc2[i][j] = 0ull;

        for (int cc = 0; cc < C_; cc += CK) {
            __syncthreads();   // protect smem from previous chunk's readers
            // fill xs: 32x128 floats, coalesced
            #pragma unroll
            for (int l = 0; l < (CK * TP) / 256; ++l) {
                int ii = tid + l * 256;
                int c = ii >> 7, p = ii & 127;
                xs[c][p] = __ldg(xbase + (size_t)(cc + c) * HW_ + p);
            }
            // fill es: 128 codes x 32 c, transposed [c][k], conflict-free (pad)
            #pragma unroll
            for (int l = 0; l < (CK * KT) / 256; ++l) {
                int ii = tid + l * 256;
                int k = ii >> 5, c = ii & 31;
                es[c][k] = __ldg(E + (size_t)(kt + k) * C_ + (cc + c));
            }
            __syncthreads();

            #pragma unroll 4
            for (int c = 0; c < CK; ++c) {
                unsigned long long axp[4], ekk[8];
                #pragma unroll
                for (int i = 0; i < 4; ++i) {
                    float2 v = *reinterpret_cast<const float2*>(&xs[c][2 * ty + 32 * i]);
                    axp[i] = pk2(v.x, v.y);
                }
                #pragma unroll
                for (int j = 0; j < 8; ++j) {
                    float e = es[c][tx + j * 16];
                    ekk[j] = pk2(e, e);
                }
                #pragma unroll
                for (int i = 0; i < 4; ++i)
                    #pragma unroll
                    for (int j = 0; j < 8; ++j)
                        ffma2(acc2[i][j], axp[i], ekk[j]);
            }
        }

        // distance + running argmin (ties -> lower index, matching jnp.argmin)
        #pragma unroll
        for (int j = 0; j < 8; ++j) {
            int k = kt + tx + j * 16;
            float e2 = g_e2[k];
            #pragma unroll
            for (int i = 0; i < 4; ++i) {
                float a0, a1;
                upk2(a0, a1, acc2[i][j]);
                float d0 = fmaf(-2.f, a0, e2);
                float d1 = fmaf(-2.f, a1, e2);
                int s0 = i * 2, s1 = i * 2 + 1;
                if (d0 < bestv[s0] || (d0 == bestv[s0] && k < besti[s0])) {
                    bestv[s0] = d0; besti[s0] = k;
                }
                if (d1 < bestv[s1] || (d1 == bestv[s1] && k < besti[s1])) {
                    bestv[s1] = d1; besti[s1] = k;
                }
            }
        }
    }

    // reduce (minval, minidx) across the 16 code-group lanes (same ty)
    #pragma unroll
    for (int s = 0; s < 8; ++s) {
        float v = bestv[s];
        int   ix = besti[s];
        #pragma unroll
        for (int off = 8; off; off >>= 1) {
            float ov = __shfl_down_sync(0xffffffffu, v, off, 16);
            int   oi = __shfl_down_sync(0xffffffffu, ix, off, 16);
            if (ov < v || (ov == v && oi < ix)) { v = ov; ix = oi; }
        }
        if (tx == 0) {
            int i = s >> 1, h = s & 1;
            g_idx[n0 + 2 * ty + 32 * i + h] = ix;
        }
    }
}

// ---------------------------------------------------------------------------
// Kernel 2: gather z_q rows, transpose-write to (b,c,h,w), accumulate loss.
// ---------------------------------------------------------------------------
#define QP 32

__global__ __launch_bounds__(256)
void vq_gather_kernel(const float* __restrict__ X, const float* __restrict__ E,
                      float* __restrict__ out) {
    __shared__ float s[QP][C_ + 5];
    __shared__ int ids[QP];

    const int tid = threadIdx.x;
    const int n0 = blockIdx.x * QP;     // 4096 % 32 == 0 -> within one b
    if (tid < QP) ids[tid] = g_idx[n0 + tid];
    __syncthreads();

    #pragma unroll
    for (int l = 0; l < (QP * C_) / 256; ++l) {
        int ii = tid + l * 256;
        int q = ii >> 8, c = ii & 255;
        s[q][c] = __ldg(E + (size_t)ids[q] * C_ + c);
    }
    __syncthreads();

    const int b = n0 / HW_, p0 = n0 % HW_;
    const size_t obase = (size_t)b * C_ * HW_ + p0;
    const int q  = tid & 31;
    const int c0 = tid >> 5;            // 0..7

    float lsum = 0.f;
    #pragma unroll
    for (int l = 0; l < C_ / 8; ++l) {
        int c = c0 + l * 8;
        float zq = s[q][c];
        size_t a = obase + (size_t)c * HW_ + q;
        float xv = __ldg(X + a);
        out[a] = zq;
        float dd = xv - zq;
        lsum = fmaf(dd, dd, lsum);
    }

    // block reduce -> double atomic
    #pragma unroll
    for (int off = 16; off; off >>= 1)
        lsum += __shfl_down_sync(0xffffffffu, lsum, off);
    __shared__ float ws[8];
    if ((tid & 31) == 0) ws[tid >> 5] = lsum;
    __syncthreads();
    if (tid < 8) {
        float v = ws[tid];
        #pragma unroll
        for (int off = 4; off; off >>= 1)
            v += __shfl_down_sync(0xffu, v, off);
        if (tid == 0) atomicAdd(&g_loss, (double)v);
    }
}

// ---------------------------------------------------------------------------
// Kernel 3: finalize loss. quantization_loss = 2 * mean((zq - x)^2)
// ---------------------------------------------------------------------------
__global__ void vq_loss_kernel(float* __restrict__ out) {
    out[ZQ_ELEMS] = (float)(2.0 * g_loss / (double)ZQ_ELEMS);
}

// ---------------------------------------------------------------------------
extern "C" void kernel_launch(void* const* d_in, const int* in_sizes, int n_in,
                              void* d_out, int out_size) {
    const float* X = (const float*)d_in[0];   // x (16,256,64,64)
    const float* E = (const float*)d_in[1];   // embeddings (1024,256)
    float* out = (float*)d_out;

    vq_e2_kernel<<<K_, 32>>>(E);
    vq_argmin_kernel<<<NPIX / TP, 256>>>(X, E);
    vq_gather_kernel<<<NPIX / QP, 256>>>(X, E, out);
    if (out_size > ZQ_ELEMS)
        vq_loss_kernel<<<1, 1>>>(out);
}